// round 3
// baseline (speedup 1.0000x reference)
#include <cuda_runtime.h>
#include <math_constants.h>

// Global spatial max-pool: [B=64, H=56, W=56, C=256] f32 NHWC -> [B=64, C=256].
//
// R3: memory-latency-bound tuning (R2 profile: issue=4%, DRAM=73%).
//  - #pragma unroll 2 on the load loop: caps front-batched MLP_p1 at ~2,
//    avoiding the cross-CTA L1tex-queue contention spread (B300 model:
//    spr 1.2x at MLP_p1=28/oe=6 -> floor 1.10 at MLP_p1<=2). Latency hiding
//    is unaffected: even MLP=2 at full occupancy = 128KB in flight per SM
//    vs ~26KB needed (BW x DRAM latency).
//  - SPLIT 14 -> 28: 1792 blocks of SPAN=112 positions. Finer granularity,
//    work-stealing smooths the residual tail (896 blocks left 8 SMs with a
//    straggler 7th block).
//  - Kept: 256-bit loads (LDG.E.256), FMNMX.F32X2 packing, fused final
//    reduce via threadfence + last-block-per-batch (counter self-resets
//    for graph replay determinism).

#define B_DIM   64
#define HW      3136           // 56*56
#define C_DIM   256
#define SPLIT   28
#define SPAN    (HW / SPLIT)   // 112 spatial positions per block
#define PHASES  8
#define ITERS   (SPAN / PHASES) // 14

__device__ float        g_partial[B_DIM * SPLIT * C_DIM];  // 1.75 MB scratch
__device__ unsigned int g_count[B_DIM];                     // zero-init, self-resetting

__global__ __launch_bounds__(256, 8)
void gmax_fused(const float* __restrict__ in, float* __restrict__ out) {
    const int blk   = blockIdx.x;            // 0..1791
    const int b     = blk / SPLIT;
    const int split = blk - b * SPLIT;
    const int t     = threadIdx.x;
    const int g     = t & 31;                // 8-channel group (32 bytes)
    const int p     = t >> 5;                // spatial phase 0..7

    const float* __restrict__ base =
        in + (((size_t)(b * HW + split * SPAN + p)) << 8) + (g << 3);

    float a0 = -CUDART_INF_F, a1 = -CUDART_INF_F, a2 = -CUDART_INF_F, a3 = -CUDART_INF_F;
    float a4 = -CUDART_INF_F, a5 = -CUDART_INF_F, a6 = -CUDART_INF_F, a7 = -CUDART_INF_F;

    #pragma unroll 2
    for (int i = 0; i < ITERS; ++i) {
        float v0, v1, v2, v3, v4, v5, v6, v7;
        asm volatile(
            "ld.global.nc.v8.f32 {%0,%1,%2,%3,%4,%5,%6,%7}, [%8];"
            : "=f"(v0), "=f"(v1), "=f"(v2), "=f"(v3),
              "=f"(v4), "=f"(v5), "=f"(v6), "=f"(v7)
            : "l"(base + (size_t)i * (PHASES * C_DIM)));
        a0 = fmaxf(a0, v0);  a1 = fmaxf(a1, v1);
        a2 = fmaxf(a2, v2);  a3 = fmaxf(a3, v3);
        a4 = fmaxf(a4, v4);  a5 = fmaxf(a5, v5);
        a6 = fmaxf(a6, v6);  a7 = fmaxf(a7, v7);
    }

    // Cross-phase reduce through smem. sm[p*256 + c], conflict-free.
    __shared__ float sm[PHASES * C_DIM];
    float* my = sm + t * 8;  // == p*256 + g*8
    my[0] = a0; my[1] = a1; my[2] = a2; my[3] = a3;
    my[4] = a4; my[5] = a5; my[6] = a6; my[7] = a7;
    __syncthreads();

    // Thread t == channel c: reduce over 8 phases, write block partial.
    {
        float m = sm[t];
        #pragma unroll
        for (int ph = 1; ph < PHASES; ++ph)
            m = fmaxf(m, sm[ph * C_DIM + t]);
        g_partial[blk * C_DIM + t] = m;
    }

    // Last-block-per-batch does the cross-split reduce (fused 2nd stage).
    __threadfence();
    __shared__ bool amLast;
    if (t == 0) {
        unsigned int old = atomicAdd(&g_count[b], 1u);
        amLast = (old == SPLIT - 1);
    }
    __syncthreads();

    if (amLast) {
        const float* part = g_partial + b * SPLIT * C_DIM;
        float m = part[t];
        #pragma unroll
        for (int s = 1; s < SPLIT; ++s)
            m = fmaxf(m, part[s * C_DIM + t]);
        out[b * C_DIM + t] = m;
        if (t == 0) g_count[b] = 0;   // self-reset for next graph replay
    }
}

extern "C" void kernel_launch(void* const* d_in, const int* in_sizes, int n_in,
                              void* d_out, int out_size) {
    const float* in  = (const float*)d_in[0];
    float*       out = (float*)d_out;
    gmax_fused<<<B_DIM * SPLIT, 256>>>(in, out);
}